// round 15
// baseline (speedup 1.0000x reference)
#include <cuda_runtime.h>
#include <cuda_bf16.h>
#include <cstdint>

#define D_MODEL 256
#define NB 16
#define ACT_OFF 10
#define LN_EPS 1e-5f
#define THREADS 128
#define WARPS 4
#define TPB 128
#define GTOK 5

typedef unsigned long long u64;

// fused actor+street+type table: combo = (a<<6)|(s<<4)|aid
__device__ float g_CT[128 * D_MODEL];

__device__ __forceinline__ u64 pack2(float lo, float hi) {
    u64 r;
    asm("mov.b64 %0, {%1, %2};" : "=l"(r)
        : "r"(__float_as_uint(lo)), "r"(__float_as_uint(hi)));
    return r;
}
__device__ __forceinline__ u64 pack2s(float v) { return pack2(v, v); }
__device__ __forceinline__ u64 fma2(u64 a, u64 b, u64 c) {
    u64 r;
    asm("fma.rn.f32x2 %0, %1, %2, %3;" : "=l"(r) : "l"(a), "l"(b), "l"(c));
    return r;
}
__device__ __forceinline__ u64 add2(u64 a, u64 b) {
    u64 r;
    asm("add.rn.f32x2 %0, %1, %2;" : "=l"(r) : "l"(a), "l"(b));
    return r;
}
__device__ __forceinline__ u64 mul2(u64 a, u64 b) {
    u64 r;
    asm("mul.rn.f32x2 %0, %1, %2;" : "=l"(r) : "l"(a), "l"(b));
    return r;
}
__device__ __forceinline__ float2 unpack2(u64 v) {
    unsigned lo, hi;
    asm("mov.b64 {%0, %1}, %2;" : "=r"(lo), "=r"(hi) : "l"(v));
    return make_float2(__uint_as_float(lo), __uint_as_float(hi));
}

// ---- tiny prep: one block per combo, fully coalesced ----
__global__ __launch_bounds__(256)
void ct_prep_kernel(const float* __restrict__ actor_emb,
                    const float* __restrict__ street_emb,
                    const float* __restrict__ type_emb)
{
    const int combo = blockIdx.x;
    const int a = combo >> 6, s = (combo >> 4) & 3, k = combo & 15;
    const int d = threadIdx.x;
    g_CT[combo * D_MODEL + d] = __ldg(actor_emb  + a * D_MODEL + d)
                              + __ldg(street_emb + s * D_MODEL + d)
                              + __ldg(type_emb   + k * D_MODEL + d);
}

__global__ __launch_bounds__(THREADS, 4)
void action_embedding_kernel(
    const int*   __restrict__ token_ids,
    const int*   __restrict__ action_actors,
    const int*   __restrict__ action_streets,
    const float* __restrict__ legal_masks,
    const float* __restrict__ mlp_w,
    const float* __restrict__ mlp_b,
    const float* __restrict__ ln_gamma,
    const float* __restrict__ ln_beta,
    float*       __restrict__ out,
    int n_tok)
{
    __shared__ float Wsh[NB * D_MODEL];        // 16 KB
    __shared__ unsigned short alist[TPB];      // (combo<<7) | tok_in_block
    __shared__ unsigned short ilist[TPB];
    __shared__ int cnts[2];

    const int tid  = threadIdx.x;
    const int warp = tid >> 5;
    const int lane = tid & 31;
    const int d0   = 4 * lane;
    const int base = blockIdx.x * TPB;

    // ---- stage W into shared ----
    #pragma unroll
    for (int i = tid; i < NB * D_MODEL / 4; i += THREADS)
        reinterpret_cast<float4*>(Wsh)[i] = __ldg(reinterpret_cast<const float4*>(mlp_w) + i);
    if (tid < 2) cnts[tid] = 0;
    __syncthreads();

    // ---- classify + compact; pack combo into the list entry ----
    {
        const int t = base + tid;
        const bool valid = (t < n_tok);
        int tk = 0;
        if (valid) tk = __ldg(token_ids + t);
        const bool act = valid && (tk >= ACT_OFF) && (tk < ACT_OFF + NB);
        int combo = 0;
        if (act) {
            int a = __ldg(action_actors  + t); a = a < 0 ? 0 : (a > 1 ? 1 : a);
            int s = __ldg(action_streets + t); s = s < 0 ? 0 : (s > 3 ? 3 : s);
            combo = (a << 6) | (s << 4) | (tk - ACT_OFF);
        }
        const unsigned am = __ballot_sync(0xFFFFFFFFu, act);
        const unsigned im = __ballot_sync(0xFFFFFFFFu, valid && !act);
        int ab = 0, ib = 0;
        if (lane == 0) {
            ab = atomicAdd(&cnts[0], __popc(am));
            ib = atomicAdd(&cnts[1], __popc(im));
        }
        ab = __shfl_sync(0xFFFFFFFFu, ab, 0);
        ib = __shfl_sync(0xFFFFFFFFu, ib, 0);
        const unsigned lt = (1u << lane) - 1u;
        if (act)        alist[ab + __popc(am & lt)] = (unsigned short)((combo << 7) | tid);
        else if (valid) ilist[ib + __popc(im & lt)] = (unsigned short)tid;
    }
    __syncthreads();
    const int n_act = cnts[0];
    const int n_in  = cnts[1];

    // ---- zero-fill inactive tokens: one warp per token ----
    {
        const float4 z = make_float4(0.f, 0.f, 0.f, 0.f);
        for (int i = warp; i < n_in; i += WARPS) {
            float4* dst = reinterpret_cast<float4*>(out + (size_t)(base + ilist[i]) * D_MODEL);
            dst[lane]      = z;
            dst[lane + 32] = z;
        }
    }

    // ---- active tokens, GTOK per warp iteration ----
    for (int g = warp * GTOK; g < n_act; g += WARPS * GTOK) {
        const int cnt = min(GTOK, n_act - g);

        int tt[GTOK], cb[GTOK];
        #pragma unroll
        for (int j = 0; j < GTOK; j++) {
            const int e = alist[g + (j < cnt ? j : 0)];
            tt[j] = base + (e & 127);
            cb[j] = e >> 7;
        }

        // accumulators as f32x2 pairs
        u64 acc[GTOK][4];
        {
            const float4 b0 = __ldg(reinterpret_cast<const float4*>(mlp_b + d0));
            const float4 b1 = __ldg(reinterpret_cast<const float4*>(mlp_b + 128 + d0));
            const u64 p0 = pack2(b0.x, b0.y), p1 = pack2(b0.z, b0.w);
            const u64 p2 = pack2(b1.x, b1.y), p3 = pack2(b1.z, b1.w);
            #pragma unroll
            for (int j = 0; j < GTOK; j++) {
                acc[j][0] = p0; acc[j][1] = p1; acc[j][2] = p2; acc[j][3] = p3;
            }
        }

        // GEMM: packed FFMA2, W from smem reused x GTOK
        #pragma unroll
        for (int kc = 0; kc < 4; kc++) {
            float4 m4[GTOK];
            #pragma unroll
            for (int j = 0; j < GTOK; j++)
                m4[j] = __ldg(reinterpret_cast<const float4*>(legal_masks + (size_t)tt[j] * NB) + kc);
            #pragma unroll
            for (int kk = 0; kk < 4; kk++) {
                const int k = kc * 4 + kk;
                const float4 w0 = *reinterpret_cast<const float4*>(&Wsh[k * D_MODEL + d0]);
                const float4 w1 = *reinterpret_cast<const float4*>(&Wsh[k * D_MODEL + 128 + d0]);
                const u64 wp0 = pack2(w0.x, w0.y), wp1 = pack2(w0.z, w0.w);
                const u64 wp2 = pack2(w1.x, w1.y), wp3 = pack2(w1.z, w1.w);
                #pragma unroll
                for (int j = 0; j < GTOK; j++) {
                    const u64 mm = pack2s((&m4[j].x)[kk]);
                    acc[j][0] = fma2(mm, wp0, acc[j][0]);
                    acc[j][1] = fma2(mm, wp1, acc[j][1]);
                    acc[j][2] = fma2(mm, wp2, acc[j][2]);
                    acc[j][3] = fma2(mm, wp3, acc[j][3]);
                }
            }
        }

        // LN stats: packed add/fma, single unpack; interleaved butterflies
        float sm[GTOK], sq[GTOK];
        #pragma unroll
        for (int j = 0; j < GTOK; j++) {
            const u64 s01 = add2(acc[j][0], acc[j][1]);
            const u64 s23 = add2(acc[j][2], acc[j][3]);
            const float2 sp = unpack2(add2(s01, s23));
            sm[j] = sp.x + sp.y;
            const u64 q = fma2(acc[j][0], acc[j][0],
                          fma2(acc[j][1], acc[j][1],
                          fma2(acc[j][2], acc[j][2],
                          mul2(acc[j][3], acc[j][3]))));
            const float2 qp = unpack2(q);
            sq[j] = qp.x + qp.y;
        }
        #pragma unroll
        for (int o = 16; o > 0; o >>= 1) {
            #pragma unroll
            for (int j = 0; j < GTOK; j++) {
                sm[j] += __shfl_xor_sync(0xFFFFFFFFu, sm[j], o);
                sq[j] += __shfl_xor_sync(0xFFFFFFFFu, sq[j], o);
            }
        }

        // gamma/beta: loop-invariant — load once per iteration, reuse for GTOK tokens
        const float4 ga0 = __ldg(reinterpret_cast<const float4*>(ln_gamma + d0));
        const float4 be0 = __ldg(reinterpret_cast<const float4*>(ln_beta  + d0));
        const float4 ga1 = __ldg(reinterpret_cast<const float4*>(ln_gamma + 128 + d0));
        const float4 be1 = __ldg(reinterpret_cast<const float4*>(ln_beta  + 128 + d0));

        // epilogue: single fused-table gather, no index loads
        #pragma unroll
        for (int j = 0; j < GTOK; j++) {
            if (j >= cnt) break;     // warp-uniform
            const float inv = 1.0f / 256.0f;
            const float mu  = sm[j] * inv;
            const float var = fmaf(sq[j], inv, -mu * mu);
            const float rs  = rsqrtf(var + LN_EPS);
            const float* ct = g_CT + cb[j] * D_MODEL;

            float4* dst = reinterpret_cast<float4*>(out + (size_t)tt[j] * D_MODEL);
            #pragma unroll
            for (int c = 0; c < 2; c++) {
                const int dd = c * 128 + d0;
                const float2 hlo = unpack2(acc[j][2*c]);
                const float2 hhi = unpack2(acc[j][2*c+1]);
                const float4 ga = c ? ga1 : ga0;
                const float4 be = c ? be1 : be0;
                const float4 e  = __ldg(reinterpret_cast<const float4*>(ct + dd));
                float4 r;
                r.x = fmaxf(fmaf((hlo.x - mu) * rs, ga.x, be.x), 0.f) + e.x;
                r.y = fmaxf(fmaf((hlo.y - mu) * rs, ga.y, be.y), 0.f) + e.y;
                r.z = fmaxf(fmaf((hhi.x - mu) * rs, ga.z, be.z), 0.f) + e.z;
                r.w = fmaxf(fmaf((hhi.y - mu) * rs, ga.w, be.w), 0.f) + e.w;
                dst[lane + 32 * c] = r;
            }
        }
    }
}

extern "C" void kernel_launch(void* const* d_in, const int* in_sizes, int n_in,
                              void* d_out, int out_size)
{
    const int*   token_ids   = (const int*)  d_in[0];
    const int*   actors      = (const int*)  d_in[1];
    const int*   streets     = (const int*)  d_in[2];
    const float* legal_masks = (const float*)d_in[3];
    const float* actor_emb   = (const float*)d_in[4];
    const float* street_emb  = (const float*)d_in[5];
    const float* type_emb    = (const float*)d_in[6];
    const float* mlp_w       = (const float*)d_in[7];
    const float* mlp_b       = (const float*)d_in[8];
    const float* ln_gamma    = (const float*)d_in[9];
    const float* ln_beta     = (const float*)d_in[10];
    float* out = (float*)d_out;

    const int n_tok  = in_sizes[0];
    ct_prep_kernel<<<128, 256>>>(actor_emb, street_emb, type_emb);
    const int blocks = (n_tok + TPB - 1) / TPB;
    action_embedding_kernel<<<blocks, THREADS>>>(
        token_ids, actors, streets, legal_masks,
        mlp_w, mlp_b, ln_gamma, ln_beta,
        out, n_tok);
}

// round 16
// speedup vs baseline: 1.0430x; 1.0430x over previous
#include <cuda_runtime.h>
#include <cuda_bf16.h>
#include <cstdint>

#define D_MODEL 256
#define NB 16
#define ACT_OFF 10
#define LN_EPS 1e-5f
#define THREADS 128
#define WARPS 4
#define TPB 128
#define GTOK 4

typedef unsigned long long u64;

// fused actor+street+type table: combo = (a<<6)|(s<<4)|aid
__device__ float g_CT[128 * D_MODEL];

__device__ __forceinline__ u64 pack2(float lo, float hi) {
    u64 r;
    asm("mov.b64 %0, {%1, %2};" : "=l"(r)
        : "r"(__float_as_uint(lo)), "r"(__float_as_uint(hi)));
    return r;
}
__device__ __forceinline__ u64 pack2s(float v) { return pack2(v, v); }
__device__ __forceinline__ u64 fma2(u64 a, u64 b, u64 c) {
    u64 r;
    asm("fma.rn.f32x2 %0, %1, %2, %3;" : "=l"(r) : "l"(a), "l"(b), "l"(c));
    return r;
}
__device__ __forceinline__ u64 add2(u64 a, u64 b) {
    u64 r;
    asm("add.rn.f32x2 %0, %1, %2;" : "=l"(r) : "l"(a), "l"(b));
    return r;
}
__device__ __forceinline__ u64 mul2(u64 a, u64 b) {
    u64 r;
    asm("mul.rn.f32x2 %0, %1, %2;" : "=l"(r) : "l"(a), "l"(b));
    return r;
}
__device__ __forceinline__ float2 unpack2(u64 v) {
    unsigned lo, hi;
    asm("mov.b64 {%0, %1}, %2;" : "=r"(lo), "=r"(hi) : "l"(v));
    return make_float2(__uint_as_float(lo), __uint_as_float(hi));
}

// ---- tiny prep: one block per combo, fully coalesced ----
__global__ __launch_bounds__(256)
void ct_prep_kernel(const float* __restrict__ actor_emb,
                    const float* __restrict__ street_emb,
                    const float* __restrict__ type_emb)
{
    const int combo = blockIdx.x;
    const int a = combo >> 6, s = (combo >> 4) & 3, k = combo & 15;
    const int d = threadIdx.x;
    g_CT[combo * D_MODEL + d] = __ldg(actor_emb  + a * D_MODEL + d)
                              + __ldg(street_emb + s * D_MODEL + d)
                              + __ldg(type_emb   + k * D_MODEL + d);
}

__global__ __launch_bounds__(THREADS, 4)
void action_embedding_kernel(
    const int*   __restrict__ token_ids,
    const int*   __restrict__ action_actors,
    const int*   __restrict__ action_streets,
    const float* __restrict__ legal_masks,
    const float* __restrict__ mlp_w,
    const float* __restrict__ mlp_b,
    const float* __restrict__ ln_gamma,
    const float* __restrict__ ln_beta,
    float*       __restrict__ out,
    int n_tok)
{
    __shared__ float Wsh[NB * D_MODEL];        // 16 KB
    __shared__ unsigned short alist[TPB];      // (combo<<7) | tok_in_block
    __shared__ unsigned short ilist[TPB];
    __shared__ int cnts[2];

    const int tid  = threadIdx.x;
    const int warp = tid >> 5;
    const int lane = tid & 31;
    const int d0   = 4 * lane;
    const int base = blockIdx.x * TPB;

    // ---- stage W into shared ----
    #pragma unroll
    for (int i = tid; i < NB * D_MODEL / 4; i += THREADS)
        reinterpret_cast<float4*>(Wsh)[i] = __ldg(reinterpret_cast<const float4*>(mlp_w) + i);
    if (tid < 2) cnts[tid] = 0;
    __syncthreads();

    // ---- classify + compact; pack combo into the list entry ----
    {
        const int t = base + tid;
        const bool valid = (t < n_tok);
        int tk = 0;
        if (valid) tk = __ldg(token_ids + t);
        const bool act = valid && (tk >= ACT_OFF) && (tk < ACT_OFF + NB);
        int combo = 0;
        if (act) {
            int a = __ldg(action_actors  + t); a = a < 0 ? 0 : (a > 1 ? 1 : a);
            int s = __ldg(action_streets + t); s = s < 0 ? 0 : (s > 3 ? 3 : s);
            combo = (a << 6) | (s << 4) | (tk - ACT_OFF);
        }
        const unsigned am = __ballot_sync(0xFFFFFFFFu, act);
        const unsigned im = __ballot_sync(0xFFFFFFFFu, valid && !act);
        int ab = 0, ib = 0;
        if (lane == 0) {
            ab = atomicAdd(&cnts[0], __popc(am));
            ib = atomicAdd(&cnts[1], __popc(im));
        }
        ab = __shfl_sync(0xFFFFFFFFu, ab, 0);
        ib = __shfl_sync(0xFFFFFFFFu, ib, 0);
        const unsigned lt = (1u << lane) - 1u;
        if (act)        alist[ab + __popc(am & lt)] = (unsigned short)((combo << 7) | tid);
        else if (valid) ilist[ib + __popc(im & lt)] = (unsigned short)tid;
    }
    __syncthreads();
    const int n_act = cnts[0];
    const int n_in  = cnts[1];

    // ---- zero-fill inactive tokens: one warp per token ----
    {
        const float4 z = make_float4(0.f, 0.f, 0.f, 0.f);
        for (int i = warp; i < n_in; i += WARPS) {
            float4* dst = reinterpret_cast<float4*>(out + (size_t)(base + ilist[i]) * D_MODEL);
            dst[lane]      = z;
            dst[lane + 32] = z;
        }
    }

    // ---- active tokens, GTOK per warp iteration ----
    for (int g = warp * GTOK; g < n_act; g += WARPS * GTOK) {
        const int cnt = min(GTOK, n_act - g);

        int tt[GTOK], cb[GTOK];
        #pragma unroll
        for (int j = 0; j < GTOK; j++) {
            const int e = alist[g + (j < cnt ? j : 0)];
            tt[j] = base + (e & 127);
            cb[j] = e >> 7;
        }

        // accumulators as f32x2 pairs
        u64 acc[GTOK][4];
        {
            const float4 b0 = __ldg(reinterpret_cast<const float4*>(mlp_b + d0));
            const float4 b1 = __ldg(reinterpret_cast<const float4*>(mlp_b + 128 + d0));
            const u64 p0 = pack2(b0.x, b0.y), p1 = pack2(b0.z, b0.w);
            const u64 p2 = pack2(b1.x, b1.y), p3 = pack2(b1.z, b1.w);
            #pragma unroll
            for (int j = 0; j < GTOK; j++) {
                acc[j][0] = p0; acc[j][1] = p1; acc[j][2] = p2; acc[j][3] = p3;
            }
        }

        // GEMM: packed FFMA2, W from smem reused x GTOK
        #pragma unroll
        for (int kc = 0; kc < 4; kc++) {
            float4 m4[GTOK];
            #pragma unroll
            for (int j = 0; j < GTOK; j++)
                m4[j] = __ldg(reinterpret_cast<const float4*>(legal_masks + (size_t)tt[j] * NB) + kc);
            #pragma unroll
            for (int kk = 0; kk < 4; kk++) {
                const int k = kc * 4 + kk;
                const float4 w0 = *reinterpret_cast<const float4*>(&Wsh[k * D_MODEL + d0]);
                const float4 w1 = *reinterpret_cast<const float4*>(&Wsh[k * D_MODEL + 128 + d0]);
                const u64 wp0 = pack2(w0.x, w0.y), wp1 = pack2(w0.z, w0.w);
                const u64 wp2 = pack2(w1.x, w1.y), wp3 = pack2(w1.z, w1.w);
                #pragma unroll
                for (int j = 0; j < GTOK; j++) {
                    const u64 mm = pack2s((&m4[j].x)[kk]);
                    acc[j][0] = fma2(mm, wp0, acc[j][0]);
                    acc[j][1] = fma2(mm, wp1, acc[j][1]);
                    acc[j][2] = fma2(mm, wp2, acc[j][2]);
                    acc[j][3] = fma2(mm, wp3, acc[j][3]);
                }
            }
        }

        // LN stats: packed add/fma, single unpack; interleaved butterflies
        float sm[GTOK], sq[GTOK];
        #pragma unroll
        for (int j = 0; j < GTOK; j++) {
            const u64 s01 = add2(acc[j][0], acc[j][1]);
            const u64 s23 = add2(acc[j][2], acc[j][3]);
            const float2 sp = unpack2(add2(s01, s23));
            sm[j] = sp.x + sp.y;
            const u64 q = fma2(acc[j][0], acc[j][0],
                          fma2(acc[j][1], acc[j][1],
                          fma2(acc[j][2], acc[j][2],
                          mul2(acc[j][3], acc[j][3]))));
            const float2 qp = unpack2(q);
            sq[j] = qp.x + qp.y;
        }
        #pragma unroll
        for (int o = 16; o > 0; o >>= 1) {
            #pragma unroll
            for (int j = 0; j < GTOK; j++) {
                sm[j] += __shfl_xor_sync(0xFFFFFFFFu, sm[j], o);
                sq[j] += __shfl_xor_sync(0xFFFFFFFFu, sq[j], o);
            }
        }

        // gamma/beta: loop-invariant — load once per iteration, reuse for GTOK tokens
        const float4 ga0 = __ldg(reinterpret_cast<const float4*>(ln_gamma + d0));
        const float4 be0 = __ldg(reinterpret_cast<const float4*>(ln_beta  + d0));
        const float4 ga1 = __ldg(reinterpret_cast<const float4*>(ln_gamma + 128 + d0));
        const float4 be1 = __ldg(reinterpret_cast<const float4*>(ln_beta  + 128 + d0));

        // epilogue: single fused-table gather, no index loads
        #pragma unroll
        for (int j = 0; j < GTOK; j++) {
            if (j >= cnt) break;     // warp-uniform
            const float inv = 1.0f / 256.0f;
            const float mu  = sm[j] * inv;
            const float var = fmaf(sq[j], inv, -mu * mu);
            const float rs  = rsqrtf(var + LN_EPS);
            const float* ct = g_CT + cb[j] * D_MODEL;

            float4* dst = reinterpret_cast<float4*>(out + (size_t)tt[j] * D_MODEL);
            #pragma unroll
            for (int c = 0; c < 2; c++) {
                const int dd = c * 128 + d0;
                const float2 hlo = unpack2(acc[j][2*c]);
                const float2 hhi = unpack2(acc[j][2*c+1]);
                const float4 ga = c ? ga1 : ga0;
                const float4 be = c ? be1 : be0;
                const float4 e  = __ldg(reinterpret_cast<const float4*>(ct + dd));
                float4 r;
                r.x = fmaxf(fmaf((hlo.x - mu) * rs, ga.x, be.x), 0.f) + e.x;
                r.y = fmaxf(fmaf((hlo.y - mu) * rs, ga.y, be.y), 0.f) + e.y;
                r.z = fmaxf(fmaf((hhi.x - mu) * rs, ga.z, be.z), 0.f) + e.z;
                r.w = fmaxf(fmaf((hhi.y - mu) * rs, ga.w, be.w), 0.f) + e.w;
                dst[lane + 32 * c] = r;
            }
        }
    }
}

extern "C" void kernel_launch(void* const* d_in, const int* in_sizes, int n_in,
                              void* d_out, int out_size)
{
    const int*   token_ids   = (const int*)  d_in[0];
    const int*   actors      = (const int*)  d_in[1];
    const int*   streets     = (const int*)  d_in[2];
    const float* legal_masks = (const float*)d_in[3];
    const float* actor_emb   = (const float*)d_in[4];
    const float* street_emb  = (const float*)d_in[5];
    const float* type_emb    = (const float*)d_in[6];
    const float* mlp_w       = (const float*)d_in[7];
    const float* mlp_b       = (const float*)d_in[8];
    const float* ln_gamma    = (const float*)d_in[9];
    const float* ln_beta     = (const float*)d_in[10];
    float* out = (float*)d_out;

    const int n_tok  = in_sizes[0];
    ct_prep_kernel<<<128, 256>>>(actor_emb, street_emb, type_emb);
    const int blocks = (n_tok + TPB - 1) / TPB;
    action_embedding_kernel<<<blocks, THREADS>>>(
        token_ids, actors, streets, legal_masks,
        mlp_w, mlp_b, ln_gamma, ln_beta,
        out, n_tok);
}

// round 17
// speedup vs baseline: 1.2597x; 1.2078x over previous
#include <cuda_runtime.h>
#include <cuda_bf16.h>
#include <cstdint>

#define D_MODEL 256
#define NB 16
#define ACT_OFF 10
#define LN_EPS 1e-5f
#define THREADS 128
#define WARPS 4
#define TPB 128
#define GTOK 4

typedef unsigned long long u64;

// fused actor+street+type table: combo = (a<<6)|(s<<4)|aid
__device__ float g_CT[128 * D_MODEL];

__device__ __forceinline__ u64 pack2(float lo, float hi) {
    u64 r;
    asm("mov.b64 %0, {%1, %2};" : "=l"(r)
        : "r"(__float_as_uint(lo)), "r"(__float_as_uint(hi)));
    return r;
}
__device__ __forceinline__ u64 pack2s(float v) { return pack2(v, v); }
__device__ __forceinline__ u64 fma2(u64 a, u64 b, u64 c) {
    u64 r;
    asm("fma.rn.f32x2 %0, %1, %2, %3;" : "=l"(r) : "l"(a), "l"(b), "l"(c));
    return r;
}
__device__ __forceinline__ float2 unpack2(u64 v) {
    unsigned lo, hi;
    asm("mov.b64 {%0, %1}, %2;" : "=r"(lo), "=r"(hi) : "l"(v));
    return make_float2(__uint_as_float(lo), __uint_as_float(hi));
}

// ---- tiny prep: one block per combo, fully coalesced ----
__global__ __launch_bounds__(256)
void ct_prep_kernel(const float* __restrict__ actor_emb,
                    const float* __restrict__ street_emb,
                    const float* __restrict__ type_emb)
{
    const int combo = blockIdx.x;
    const int a = combo >> 6, s = (combo >> 4) & 3, k = combo & 15;
    const int d = threadIdx.x;
    g_CT[combo * D_MODEL + d] = __ldg(actor_emb  + a * D_MODEL + d)
                              + __ldg(street_emb + s * D_MODEL + d)
                              + __ldg(type_emb   + k * D_MODEL + d);
}

__global__ __launch_bounds__(THREADS, 4)
void action_embedding_kernel(
    const int*   __restrict__ token_ids,
    const int*   __restrict__ action_actors,
    const int*   __restrict__ action_streets,
    const float* __restrict__ legal_masks,
    const float* __restrict__ mlp_w,
    const float* __restrict__ mlp_b,
    const float* __restrict__ ln_gamma,
    const float* __restrict__ ln_beta,
    float*       __restrict__ out,
    int n_tok)
{
    __shared__ float  Wsh[NB * D_MODEL];       // 16 KB
    __shared__ float4 Msh[TPB][4];             // 8 KB: compacted active-token masks
    __shared__ unsigned short alist[TPB];      // (combo<<7) | tok_in_block
    __shared__ unsigned short ilist[TPB];
    __shared__ int cnts[2];

    const int tid  = threadIdx.x;
    const int warp = tid >> 5;
    const int lane = tid & 31;
    const int d0   = 4 * lane;
    const int base = blockIdx.x * TPB;

    // ---- stage W into shared ----
    #pragma unroll
    for (int i = tid; i < NB * D_MODEL / 4; i += THREADS)
        reinterpret_cast<float4*>(Wsh)[i] = __ldg(reinterpret_cast<const float4*>(mlp_w) + i);
    if (tid < 2) cnts[tid] = 0;
    __syncthreads();

    // ---- classify + compact; pack combo into the list entry ----
    {
        const int t = base + tid;
        const bool valid = (t < n_tok);
        int tk = 0;
        if (valid) tk = __ldg(token_ids + t);
        const bool act = valid && (tk >= ACT_OFF) && (tk < ACT_OFF + NB);
        int combo = 0;
        if (act) {
            int a = __ldg(action_actors  + t); a = a < 0 ? 0 : (a > 1 ? 1 : a);
            int s = __ldg(action_streets + t); s = s < 0 ? 0 : (s > 3 ? 3 : s);
            combo = (a << 6) | (s << 4) | (tk - ACT_OFF);
        }
        const unsigned am = __ballot_sync(0xFFFFFFFFu, act);
        const unsigned im = __ballot_sync(0xFFFFFFFFu, valid && !act);
        int ab = 0, ib = 0;
        if (lane == 0) {
            ab = atomicAdd(&cnts[0], __popc(am));
            ib = atomicAdd(&cnts[1], __popc(im));
        }
        ab = __shfl_sync(0xFFFFFFFFu, ab, 0);
        ib = __shfl_sync(0xFFFFFFFFu, ib, 0);
        const unsigned lt = (1u << lane) - 1u;
        if (act)        alist[ab + __popc(am & lt)] = (unsigned short)((combo << 7) | tid);
        else if (valid) ilist[ib + __popc(im & lt)] = (unsigned short)tid;
    }
    __syncthreads();
    const int n_act = cnts[0];
    const int n_in  = cnts[1];

    // ---- stage compacted masks into shared (high-MLP batched prologue) ----
    for (int i = tid; i < n_act; i += THREADS) {
        const int t = base + (alist[i] & 127);
        const float4* lm = reinterpret_cast<const float4*>(legal_masks + (size_t)t * NB);
        Msh[i][0] = __ldg(lm + 0);
        Msh[i][1] = __ldg(lm + 1);
        Msh[i][2] = __ldg(lm + 2);
        Msh[i][3] = __ldg(lm + 3);
    }

    // ---- zero-fill inactive tokens: one warp per token (overlaps mask staging) ----
    {
        const float4 z = make_float4(0.f, 0.f, 0.f, 0.f);
        for (int i = warp; i < n_in; i += WARPS) {
            float4* dst = reinterpret_cast<float4*>(out + (size_t)(base + ilist[i]) * D_MODEL);
            dst[lane]      = z;
            dst[lane + 32] = z;
        }
    }
    __syncthreads();

    // ---- active tokens, GTOK per warp iteration ----
    for (int g = warp * GTOK; g < n_act; g += WARPS * GTOK) {
        const int cnt = min(GTOK, n_act - g);

        int tt[GTOK], cb[GTOK], mi[GTOK];
        #pragma unroll
        for (int j = 0; j < GTOK; j++) {
            const int idx = g + (j < cnt ? j : 0);
            const int e = alist[idx];
            tt[j] = base + (e & 127);
            cb[j] = e >> 7;
            mi[j] = idx;
        }

        // accumulators as f32x2 pairs
        u64 acc[GTOK][4];
        {
            const float4 b0 = __ldg(reinterpret_cast<const float4*>(mlp_b + d0));
            const float4 b1 = __ldg(reinterpret_cast<const float4*>(mlp_b + 128 + d0));
            const u64 p0 = pack2(b0.x, b0.y), p1 = pack2(b0.z, b0.w);
            const u64 p2 = pack2(b1.x, b1.y), p3 = pack2(b1.z, b1.w);
            #pragma unroll
            for (int j = 0; j < GTOK; j++) {
                acc[j][0] = p0; acc[j][1] = p1; acc[j][2] = p2; acc[j][3] = p3;
            }
        }

        // GEMM: packed FFMA2; masks from smem (uniform LDS broadcast), W from smem
        #pragma unroll
        for (int kc = 0; kc < 4; kc++) {
            float4 m4[GTOK];
            #pragma unroll
            for (int j = 0; j < GTOK; j++)
                m4[j] = Msh[mi[j]][kc];
            #pragma unroll
            for (int kk = 0; kk < 4; kk++) {
                const int k = kc * 4 + kk;
                const float4 w0 = *reinterpret_cast<const float4*>(&Wsh[k * D_MODEL + d0]);
                const float4 w1 = *reinterpret_cast<const float4*>(&Wsh[k * D_MODEL + 128 + d0]);
                const u64 wp0 = pack2(w0.x, w0.y), wp1 = pack2(w0.z, w0.w);
                const u64 wp2 = pack2(w1.x, w1.y), wp3 = pack2(w1.z, w1.w);
                #pragma unroll
                for (int j = 0; j < GTOK; j++) {
                    const u64 mm = pack2s((&m4[j].x)[kk]);
                    acc[j][0] = fma2(mm, wp0, acc[j][0]);
                    acc[j][1] = fma2(mm, wp1, acc[j][1]);
                    acc[j][2] = fma2(mm, wp2, acc[j][2]);
                    acc[j][3] = fma2(mm, wp3, acc[j][3]);
                }
            }
        }

        // LN stats: transient unpack, interleaved butterflies (round-13 form)
        float sm[GTOK], sq[GTOK];
        #pragma unroll
        for (int j = 0; j < GTOK; j++) {
            const float2 a0 = unpack2(acc[j][0]);
            const float2 a1 = unpack2(acc[j][1]);
            const float2 a2 = unpack2(acc[j][2]);
            const float2 a3 = unpack2(acc[j][3]);
            sm[j] = (a0.x + a0.y) + (a1.x + a1.y) + (a2.x + a2.y) + (a3.x + a3.y);
            sq[j] = fmaf(a0.x, a0.x, fmaf(a0.y, a0.y,
                    fmaf(a1.x, a1.x, fmaf(a1.y, a1.y,
                    fmaf(a2.x, a2.x, fmaf(a2.y, a2.y,
                    fmaf(a3.x, a3.x, a3.y * a3.y)))))));
        }
        #pragma unroll
        for (int o = 16; o > 0; o >>= 1) {
            #pragma unroll
            for (int j = 0; j < GTOK; j++) {
                sm[j] += __shfl_xor_sync(0xFFFFFFFFu, sm[j], o);
                sq[j] += __shfl_xor_sync(0xFFFFFFFFu, sq[j], o);
            }
        }

        // epilogue: single fused-table gather, no index loads (round-13 form)
        #pragma unroll
        for (int j = 0; j < GTOK; j++) {
            if (j >= cnt) break;     // warp-uniform
            const float inv = 1.0f / 256.0f;
            const float mu  = sm[j] * inv;
            const float var = fmaf(sq[j], inv, -mu * mu);
            const float rs  = rsqrtf(var + LN_EPS);
            const float* ct = g_CT + cb[j] * D_MODEL;

            float4* dst = reinterpret_cast<float4*>(out + (size_t)tt[j] * D_MODEL);
            #pragma unroll
            for (int c = 0; c < 2; c++) {
                const int dd = c * 128 + d0;
                const float2 hlo = unpack2(acc[j][2*c]);
                const float2 hhi = unpack2(acc[j][2*c+1]);
                const float4 ga = __ldg(reinterpret_cast<const float4*>(ln_gamma + dd));
                const float4 be = __ldg(reinterpret_cast<const float4*>(ln_beta  + dd));
                const float4 e  = __ldg(reinterpret_cast<const float4*>(ct + dd));
                float4 r;
                r.x = fmaxf(fmaf((hlo.x - mu) * rs, ga.x, be.x), 0.f) + e.x;
                r.y = fmaxf(fmaf((hlo.y - mu) * rs, ga.y, be.y), 0.f) + e.y;
                r.z = fmaxf(fmaf((hhi.x - mu) * rs, ga.z, be.z), 0.f) + e.z;
                r.w = fmaxf(fmaf((hhi.y - mu) * rs, ga.w, be.w), 0.f) + e.w;
                dst[lane + 32 * c] = r;
            }
        }
    }
}

extern "C" void kernel_launch(void* const* d_in, const int* in_sizes, int n_in,
                              void* d_out, int out_size)
{
    const int*   token_ids   = (const int*)  d_in[0];
    const int*   actors      = (const int*)  d_in[1];
    const int*   streets     = (const int*)  d_in[2];
    const float* legal_masks = (const float*)d_in[3];
    const float* actor_emb   = (const float*)d_in[4];
    const float* street_emb  = (const float*)d_in[5];
    const float* type_emb    = (const float*)d_in[6];
    const float* mlp_w       = (const float*)d_in[7];
    const float* mlp_b       = (const float*)d_in[8];
    const float* ln_gamma    = (const float*)d_in[9];
    const float* ln_beta     = (const float*)d_in[10];
    float* out = (float*)d_out;

    const int n_tok  = in_sizes[0];
    ct_prep_kernel<<<128, 256>>>(actor_emb, street_emb, type_emb);
    const int blocks = (n_tok + TPB - 1) / TPB;
    action_embedding_kernel<<<blocks, THREADS>>>(
        token_ids, actors, streets, legal_masks,
        mlp_w, mlp_b, ln_gamma, ln_beta,
        out, n_tok);
}